// round 3
// baseline (speedup 1.0000x reference)
#include <cuda_runtime.h>
#include <cuda_fp16.h>
#include <cstdint>

#define NTHREADS 256
#define TILE_B   16
#define NBLOCKS  (4096 / TILE_B)   // 256

// Shared memory byte offsets (single char array, 16B aligned regions)
#define OFB_W0P 0        // f32 64*132          = 33792 B (reused for W3 at root)
#define OFB_C0  33792    // f32 64*24           = 6144 B
#define OFB_WF  39936    // f32 32              = 128 B
#define OFB_H0  40064    // half 64*324 (m-stride 324h, b-stride 20h) = 41472 B
#define OFB_H1  81536    // f32 16*132          = 8448 B
#define OFB_H2  89984    // f32 16*132          = 8448 B
#define OFB_HR  98432    // f32 256             = 1024 B
#define SMEM_BYTES 99456

// Folded leaf weights: W0p[m,g,h] = Wg[m,g]*W0[m,g,h]; c0[m,h] = sum_g bg*W0
__device__ __align__(16) float g_W0p[512 * 128];
__device__ __align__(16) float g_c0[512 * 16];

using ull = unsigned long long;

__device__ __forceinline__ ull pack2(float x, float y) {
    ull r; asm("mov.b64 %0,{%1,%2};" : "=l"(r) : "f"(x), "f"(y)); return r;
}
__device__ __forceinline__ void fma2(ull& d, ull a, ull b) {
    asm("fma.rn.f32x2 %0,%1,%2,%3;" : "=l"(d) : "l"(a), "l"(b), "l"(d));
}
__device__ __forceinline__ ull add2(ull a, ull b) {
    ull r; asm("add.rn.f32x2 %0,%1,%2;" : "=l"(r) : "l"(a), "l"(b)); return r;
}
__device__ __forceinline__ float2 unpack2(ull v) {
    float2 r; asm("mov.b64 {%0,%1},%2;" : "=f"(r.x), "=f"(r.y) : "l"(v)); return r;
}
// sigmoid(x) = 0.5*tanh(0.5x)+0.5 -> MUFU.TANH + FFMA
__device__ __forceinline__ float sigmoidf_(float v) {
    float t;
    asm("tanh.approx.f32 %0, %1;" : "=f"(t) : "f"(v * 0.5f));
    return fmaf(t, 0.5f, 0.5f);
}

__device__ __forceinline__ void copy4(float* dst, const float* src, int n) {
    const float4* s4 = (const float4*)src;
    float4* d4 = (float4*)dst;
    for (int i = threadIdx.x; i < (n >> 2); i += NTHREADS) d4[i] = s4[i];
}

// ---------------------------------------------------------------------------
__global__ void prep_kernel(const float* __restrict__ Wg,
                            const float* __restrict__ bg,
                            const float* __restrict__ W0) {
    int i = blockIdx.x * blockDim.x + threadIdx.x;
    if (i >= 512 * 16) return;
    int m = i >> 4, h = i & 15;
    float c = 0.f;
#pragma unroll
    for (int g = 0; g < 8; ++g) {
        float w = W0[(m * 8 + g) * 16 + h];
        g_W0p[m * 128 + g * 16 + h] = Wg[m * 8 + g] * w;
        c += bg[m * 8 + g] * w;
    }
    g_c0[i] = c;
}

// ---------------------------------------------------------------------------
extern __shared__ __align__(16) char smem_raw[];

__global__ void __launch_bounds__(NTHREADS, 2)
fused_kernel(const float* __restrict__ x,
             const float* __restrict__ W1,
             const float* __restrict__ W2,
             const float* __restrict__ W3,
             const float* __restrict__ Wf,
             float* __restrict__ out) {
    float*  sW0p = (float*)(smem_raw + OFB_W0P);
    float*  sC0  = (float*)(smem_raw + OFB_C0);
    float*  sWf  = (float*)(smem_raw + OFB_WF);
    __half* sH0  = (__half*)(smem_raw + OFB_H0);  // m*324 + b*20 + h (half units)
    float*  sH1  = (float*)(smem_raw + OFB_H1);   // b*132 + j*16 + h
    float*  sH2  = (float*)(smem_raw + OFB_H2);   // b*132 + s2*16 + h
    float*  sHr  = (float*)(smem_raw + OFB_HR);

    const int tid = threadIdx.x;
    const int b0  = blockIdx.x * TILE_B;

    if (tid < 16) sWf[tid] = Wf[tid];

#pragma unroll 1
    for (int s2 = 0; s2 < 8; ++s2) {
        __syncthreads();
        // ---- Stage W0p (stride 132) + C0 (stride 24) ----
        {
            const float4* src = (const float4*)(g_W0p + s2 * 8192);
            for (int i4 = tid; i4 < 2048; i4 += NTHREADS) {
                int m = i4 >> 5, r4 = i4 & 31;
                *(float4*)(sW0p + m * 132 + r4 * 4) = src[i4];
            }
            const float4* csrc = (const float4*)(g_c0 + s2 * 1024);
            for (int i4 = tid; i4 < 256; i4 += NTHREADS) {
                int m = i4 >> 2, r4 = i4 & 3;
                *(float4*)(sC0 + m * 24 + r4 * 4) = csrc[i4];
            }
        }
        __syncthreads();

        // ---- Level 0: item=(bh 0..7, m 0..63); 2 b rows per item, 2 items/thread
        {
#pragma unroll
            for (int it = 0; it < 2; ++it) {
                int idx = tid + it * NTHREADS;
                int bh = idx & 7, m = idx >> 3;
                int bA = bh * 2;
                float xs[2][8];
#pragma unroll
                for (int i = 0; i < 2; ++i) {
                    const float4* xr = (const float4*)x
                        + (((size_t)(b0 + bA + i)) << 10) + ((s2 * 64 + m) << 1);
                    float4 u = xr[0], v = xr[1];
                    xs[i][0] = u.x; xs[i][1] = u.y; xs[i][2] = u.z; xs[i][3] = u.w;
                    xs[i][4] = v.x; xs[i][5] = v.y; xs[i][6] = v.z; xs[i][7] = v.w;
                }
                ull acc[2][8];
                const ulonglong2* c0p = (const ulonglong2*)(sC0 + m * 24);
#pragma unroll
                for (int p = 0; p < 4; ++p) {
                    ulonglong2 c = c0p[p];
                    acc[0][2*p] = c.x; acc[0][2*p+1] = c.y;
                    acc[1][2*p] = c.x; acc[1][2*p+1] = c.y;
                }
                const ulonglong2* wp = (const ulonglong2*)(sW0p + m * 132);
#pragma unroll
                for (int g = 0; g < 8; ++g) {
                    ulonglong2 wA = wp[g*4+0], wB = wp[g*4+1];
                    ulonglong2 wC = wp[g*4+2], wD = wp[g*4+3];
#pragma unroll
                    for (int i = 0; i < 2; ++i) {
                        ull ag = pack2(xs[i][g], xs[i][g]);
                        fma2(acc[i][0], ag, wA.x); fma2(acc[i][1], ag, wA.y);
                        fma2(acc[i][2], ag, wB.x); fma2(acc[i][3], ag, wB.y);
                        fma2(acc[i][4], ag, wC.x); fma2(acc[i][5], ag, wC.y);
                        fma2(acc[i][6], ag, wD.x); fma2(acc[i][7], ag, wD.y);
                    }
                }
#pragma unroll
                for (int i = 0; i < 2; ++i) {
                    __half* o = sH0 + m * 324 + (bA + i) * 20;
#pragma unroll
                    for (int p = 0; p < 4; ++p) {
                        float2 v0 = unpack2(acc[i][2*p]);
                        float2 v1 = unpack2(acc[i][2*p+1]);
                        __half2 h0 = __floats2half2_rn(sigmoidf_(v0.x), sigmoidf_(v0.y));
                        __half2 h1 = __floats2half2_rn(sigmoidf_(v1.x), sigmoidf_(v1.y));
                        uint2 st;
                        st.x = *(unsigned*)&h0; st.y = *(unsigned*)&h1;
                        *(uint2*)(o + p * 4) = st;
                    }
                }
            }
        }
        __syncthreads();

        // ---- Level 1: thread=(kk 0..3 | q): q=(bq 0..3, hp 0..1, j 0..7)
        //      each thread: 4 b (bq*4..+3) x 8 h (hp*8..) x 32 k (kk*32..)
        {
            const int kk = tid & 3;
            const int q  = tid >> 2;
            const int bq = q & 3;
            const int hp = (q >> 2) & 1;
            const int j  = q >> 3;
            const float*  wg = W1 + ((s2 * 8 + j) * 128 + kk * 32) * 16 + hp * 8;
            const __half* aB = sH0 + (j * 8 + kk * 2) * 324 + (bq * 4) * 20;
            ull acc[4][4];
#pragma unroll
            for (int i = 0; i < 4; ++i)
#pragma unroll
                for (int p = 0; p < 4; ++p) acc[i][p] = 0ull;

#pragma unroll
            for (int cc = 0; cc < 2; ++cc) {
                const __half* aC = aB + cc * 324;
                const float*  wC = wg + cc * 256;
#pragma unroll
                for (int k4 = 0; k4 < 4; ++k4) {
                    ulonglong2 w0a = __ldg((const ulonglong2*)(wC + (k4*4+0)*16));
                    ulonglong2 w0b = __ldg((const ulonglong2*)(wC + (k4*4+0)*16 + 4));
                    ulonglong2 w1a = __ldg((const ulonglong2*)(wC + (k4*4+1)*16));
                    ulonglong2 w1b = __ldg((const ulonglong2*)(wC + (k4*4+1)*16 + 4));
                    ulonglong2 w2a = __ldg((const ulonglong2*)(wC + (k4*4+2)*16));
                    ulonglong2 w2b = __ldg((const ulonglong2*)(wC + (k4*4+2)*16 + 4));
                    ulonglong2 w3a = __ldg((const ulonglong2*)(wC + (k4*4+3)*16));
                    ulonglong2 w3b = __ldg((const ulonglong2*)(wC + (k4*4+3)*16 + 4));
#pragma unroll
                    for (int i = 0; i < 4; ++i) {
                        uint2 ar = *(const uint2*)(aC + i * 20 + k4 * 4);
                        __half2 ha = *(__half2*)&ar.x;
                        __half2 hb = *(__half2*)&ar.y;
                        float2 a01 = __half22float2(ha);
                        float2 a23 = __half22float2(hb);
                        ull a0 = pack2(a01.x, a01.x), a1 = pack2(a01.y, a01.y);
                        ull a2 = pack2(a23.x, a23.x), a3 = pack2(a23.y, a23.y);
                        fma2(acc[i][0], a0, w0a.x); fma2(acc[i][1], a0, w0a.y);
                        fma2(acc[i][2], a0, w0b.x); fma2(acc[i][3], a0, w0b.y);
                        fma2(acc[i][0], a1, w1a.x); fma2(acc[i][1], a1, w1a.y);
                        fma2(acc[i][2], a1, w1b.x); fma2(acc[i][3], a1, w1b.y);
                        fma2(acc[i][0], a2, w2a.x); fma2(acc[i][1], a2, w2a.y);
                        fma2(acc[i][2], a2, w2b.x); fma2(acc[i][3], a2, w2b.y);
                        fma2(acc[i][0], a3, w3a.x); fma2(acc[i][1], a3, w3a.y);
                        fma2(acc[i][2], a3, w3b.x); fma2(acc[i][3], a3, w3b.y);
                    }
                }
            }
            // reduce over kk (tid bits 0..1) via butterfly shuffle, f32x2 adds
#pragma unroll
            for (int i = 0; i < 4; ++i)
#pragma unroll
                for (int p = 0; p < 4; ++p) {
                    ull v = acc[i][p];
                    v = add2(v, __shfl_xor_sync(0xffffffffu, v, 1));
                    v = add2(v, __shfl_xor_sync(0xffffffffu, v, 2));
                    acc[i][p] = v;
                }
            if (kk == 0) {
#pragma unroll
                for (int i = 0; i < 4; ++i) {
                    int b = bq * 4 + i;
                    float* o = sH1 + b * 132 + j * 16 + hp * 8;
                    float2 v0 = unpack2(acc[i][0]), v1 = unpack2(acc[i][1]);
                    float2 v2 = unpack2(acc[i][2]), v3 = unpack2(acc[i][3]);
                    float4 r0, r1;
                    r0.x = sigmoidf_(v0.x); r0.y = sigmoidf_(v0.y);
                    r0.z = sigmoidf_(v1.x); r0.w = sigmoidf_(v1.y);
                    r1.x = sigmoidf_(v2.x); r1.y = sigmoidf_(v2.y);
                    r1.z = sigmoidf_(v3.x); r1.w = sigmoidf_(v3.y);
                    *(float4*)o = r0;
                    *(float4*)(o + 4) = r1;
                }
            }
        }
        __syncthreads();

        // ---- Level 2: 128 threads, thread=(b 0..15, hp2 0..7); W2 via L1/L2 ----
        if (tid < 128) {
            const int b = tid & 15, hp2 = tid >> 4;
            const float* in = sH1 + b * 132;
            const float* w  = W2 + s2 * 2048 + hp2 * 2;
            ull acc = 0ull;
#pragma unroll
            for (int k4 = 0; k4 < 32; ++k4) {
                float4 a4 = *(const float4*)(in + k4 * 4);
                float av[4] = {a4.x, a4.y, a4.z, a4.w};
#pragma unroll
                for (int r = 0; r < 4; ++r) {
                    ull ad = pack2(av[r], av[r]);
                    ull wv = __ldg((const ull*)(w + (k4 * 4 + r) * 16));
                    fma2(acc, ad, wv);
                }
            }
            float2 v = unpack2(acc);
            float2 s; s.x = sigmoidf_(v.x); s.y = sigmoidf_(v.y);
            *(float2*)(sH2 + b * 132 + s2 * 16 + hp2 * 2) = s;
        }
    }
    __syncthreads();
    // W0p region is dead now: reuse it for W3
    copy4(sW0p, W3, 2048);
    __syncthreads();

    // ---- Root: 128 -> 16, sigmoid, scale by Wf ----
    {
        const int b = tid & 15, h = tid >> 4;
        const float* in = sH2 + b * 132;
        float acc = 0.f;
#pragma unroll
        for (int k4 = 0; k4 < 32; ++k4) {
            float4 a4 = *(const float4*)(in + k4 * 4);
            acc = fmaf(a4.x, sW0p[(k4 * 4 + 0) * 16 + h], acc);
            acc = fmaf(a4.y, sW0p[(k4 * 4 + 1) * 16 + h], acc);
            acc = fmaf(a4.z, sW0p[(k4 * 4 + 2) * 16 + h], acc);
            acc = fmaf(a4.w, sW0p[(k4 * 4 + 3) * 16 + h], acc);
        }
        sHr[b * 16 + h] = sigmoidf_(acc) * sWf[h];
    }
    __syncthreads();
    if (tid < 16) {
        const float* r = sHr + tid * 16;
        float acc = 0.f;
#pragma unroll
        for (int h = 0; h < 16; ++h) acc += r[h];
        out[b0 + tid] = acc;
    }
}

// ---------------------------------------------------------------------------
extern "C" void kernel_launch(void* const* d_in, const int* in_sizes, int n_in,
                              void* d_out, int out_size) {
    const float* x  = (const float*)d_in[0];
    const float* Wg = (const float*)d_in[1];
    const float* bg = (const float*)d_in[2];
    const float* W0 = (const float*)d_in[3];
    const float* W1 = (const float*)d_in[4];
    const float* W2 = (const float*)d_in[5];
    const float* W3 = (const float*)d_in[6];
    const float* Wf = (const float*)d_in[7];
    float* out = (float*)d_out;

    cudaFuncSetAttribute(fused_kernel,
                         cudaFuncAttributeMaxDynamicSharedMemorySize, SMEM_BYTES);

    prep_kernel<<<32, 256>>>(Wg, bg, W0);
    fused_kernel<<<NBLOCKS, NTHREADS, SMEM_BYTES>>>(x, W1, W2, W3, Wf, out);
}

// round 6
// speedup vs baseline: 1.1124x; 1.1124x over previous
#include <cuda_runtime.h>
#include <cuda_fp16.h>
#include <cstdint>

#define NTHREADS 256
#define TILE_B   16
#define NBLOCKS  (4096 / TILE_B)   // 256

// Shared memory byte offsets (16B aligned)
#define OFB_W1  0        // f32 4*2064 = 8256 floats = 33024 B (quarter-padded; reused for W3)
#define OFB_W0P 33024    // f32 32*132 = 4224 floats = 16896 B
#define OFB_C0  49920    // f32 32*24  = 768  floats = 3072 B
#define OFB_H0  52992    // half 32*324 = 10368 halves = 20736 B (m-str 324h, b-str 20h)
#define OFB_H1  73728    // f32 16*132 = 8448 B
#define OFB_H2  82176    // f32 16*132 = 8448 B
#define OFB_HR  90624    // f32 256 = 1024 B
#define OFB_WF  91648    // 128 B
#define SMEM_BYTES 91776

// Folded leaf weights: W0p[m,g,h] = Wg[m,g]*W0[m,g,h]; c0[m,h] = sum_g bg*W0
__device__ __align__(16) float g_W0p[512 * 128];
__device__ __align__(16) float g_c0[512 * 16];

using ull = unsigned long long;

__device__ __forceinline__ ull pack2(float x, float y) {
    ull r; asm("mov.b64 %0,{%1,%2};" : "=l"(r) : "f"(x), "f"(y)); return r;
}
__device__ __forceinline__ void fma2(ull& d, ull a, ull b) {
    asm("fma.rn.f32x2 %0,%1,%2,%3;" : "=l"(d) : "l"(a), "l"(b), "l"(d));
}
__device__ __forceinline__ ull add2(ull a, ull b) {
    ull r; asm("add.rn.f32x2 %0,%1,%2;" : "=l"(r) : "l"(a), "l"(b)); return r;
}
__device__ __forceinline__ float2 unpack2(ull v) {
    float2 r; asm("mov.b64 {%0,%1},%2;" : "=f"(r.x), "=f"(r.y) : "l"(v)); return r;
}
__device__ __forceinline__ float sigmoidf_(float v) {
    float t;
    asm("tanh.approx.f32 %0, %1;" : "=f"(t) : "f"(v * 0.5f));
    return fmaf(t, 0.5f, 0.5f);
}

__device__ __forceinline__ void copy4(float* dst, const float* src, int n) {
    const float4* s4 = (const float4*)src;
    float4* d4 = (float4*)dst;
    for (int i = threadIdx.x; i < (n >> 2); i += NTHREADS) d4[i] = s4[i];
}

// ---------------------------------------------------------------------------
__global__ void prep_kernel(const float* __restrict__ Wg,
                            const float* __restrict__ bg,
                            const float* __restrict__ W0) {
    int i = blockIdx.x * blockDim.x + threadIdx.x;
    if (i >= 512 * 16) return;
    int m = i >> 4, h = i & 15;
    float c = 0.f;
#pragma unroll
    for (int g = 0; g < 8; ++g) {
        float w = W0[(m * 8 + g) * 16 + h];
        g_W0p[m * 128 + g * 16 + h] = Wg[m * 8 + g] * w;
        c += bg[m * 8 + g] * w;
    }
    g_c0[i] = c;
}

// ---------------------------------------------------------------------------
extern __shared__ __align__(16) char smem_raw[];

__global__ void __launch_bounds__(NTHREADS, 2)
fused_kernel(const float* __restrict__ x,
             const float* __restrict__ W1,
             const float* __restrict__ W2,
             const float* __restrict__ W3,
             const float* __restrict__ Wf,
             float* __restrict__ out) {
    float*  sW1  = (float*)(smem_raw + OFB_W1);   // [jl]*2064 + [k>>5]*516 + [k&31]*16 + h
    float*  sW0p = (float*)(smem_raw + OFB_W0P);  // m*132
    float*  sC0  = (float*)(smem_raw + OFB_C0);   // m*24
    __half* sH0  = (__half*)(smem_raw + OFB_H0);  // m*324 + b*20 + h (halves)
    float*  sH1  = (float*)(smem_raw + OFB_H1);   // b*132 + j*16 + h
    float*  sH2  = (float*)(smem_raw + OFB_H2);   // b*132 + s2*16 + h
    float*  sHr  = (float*)(smem_raw + OFB_HR);
    float*  sWf  = (float*)(smem_raw + OFB_WF);

    const int tid = threadIdx.x;
    const int b0  = blockIdx.x * TILE_B;

    if (tid < 16) sWf[tid] = Wf[tid];

#pragma unroll 1
    for (int s2 = 0; s2 < 8; ++s2) {
#pragma unroll 1
        for (int half = 0; half < 2; ++half) {
            __syncthreads();   // previous consumers of sW1/sW0p/sH0 are done
            // ---- Stage this half's weights ----
            {
                const float4* w1src = (const float4*)(W1 + (size_t)(s2 * 8 + half * 4) * 2048);
                for (int i4 = tid; i4 < 2048; i4 += NTHREADS) {
                    int jl = i4 >> 9, rem = i4 & 511;
                    int k = rem >> 2, h4 = rem & 3;
                    *(float4*)(sW1 + jl * 2064 + (k >> 5) * 516 + (k & 31) * 16 + h4 * 4)
                        = w1src[i4];
                }
                const float4* src = (const float4*)(g_W0p + (s2 * 64 + half * 32) * 128);
                for (int i4 = tid; i4 < 1024; i4 += NTHREADS) {
                    int m = i4 >> 5, r4 = i4 & 31;
                    *(float4*)(sW0p + m * 132 + r4 * 4) = src[i4];
                }
                const float4* csrc = (const float4*)(g_c0 + (s2 * 64 + half * 32) * 16);
                for (int i4 = tid; i4 < 128; i4 += NTHREADS) {
                    int m = i4 >> 2, r4 = i4 & 3;
                    *(float4*)(sC0 + m * 24 + r4 * 4) = csrc[i4];
                }
            }
            __syncthreads();

            // ---- Level 0: thread = (bp 0..7, m 0..31); 2 batch rows each ----
            {
                const int bp = tid & 7;
                const int m  = tid >> 3;       // 0..31
                const int gene2 = (s2 * 64 + half * 32 + m) << 1;  // float4 units
                float xs[2][8];
#pragma unroll
                for (int i = 0; i < 2; ++i) {
                    const float4* xr = (const float4*)x
                        + (((size_t)(b0 + bp * 2 + i)) << 10) + gene2;
                    float4 u = xr[0], v = xr[1];
                    xs[i][0] = u.x; xs[i][1] = u.y; xs[i][2] = u.z; xs[i][3] = u.w;
                    xs[i][4] = v.x; xs[i][5] = v.y; xs[i][6] = v.z; xs[i][7] = v.w;
                }
                ull acc[2][8];
                const ulonglong2* c0p = (const ulonglong2*)(sC0 + m * 24);
#pragma unroll
                for (int p = 0; p < 4; ++p) {
                    ulonglong2 c = c0p[p];
                    acc[0][2*p] = c.x; acc[0][2*p+1] = c.y;
                    acc[1][2*p] = c.x; acc[1][2*p+1] = c.y;
                }
                const ulonglong2* wp = (const ulonglong2*)(sW0p + m * 132);
#pragma unroll
                for (int g = 0; g < 8; ++g) {
                    ulonglong2 wA = wp[g*4+0], wB = wp[g*4+1];
                    ulonglong2 wC = wp[g*4+2], wD = wp[g*4+3];
#pragma unroll
                    for (int i = 0; i < 2; ++i) {
                        ull ag = pack2(xs[i][g], xs[i][g]);
                        fma2(acc[i][0], ag, wA.x); fma2(acc[i][1], ag, wA.y);
                        fma2(acc[i][2], ag, wB.x); fma2(acc[i][3], ag, wB.y);
                        fma2(acc[i][4], ag, wC.x); fma2(acc[i][5], ag, wC.y);
                        fma2(acc[i][6], ag, wD.x); fma2(acc[i][7], ag, wD.y);
                    }
                }
#pragma unroll
                for (int i = 0; i < 2; ++i) {
                    __half* o = sH0 + m * 324 + (bp * 2 + i) * 20;
#pragma unroll
                    for (int p = 0; p < 4; ++p) {
                        float2 v0 = unpack2(acc[i][2*p]);
                        float2 v1 = unpack2(acc[i][2*p+1]);
                        __half2 h0v = __floats2half2_rn(sigmoidf_(v0.x), sigmoidf_(v0.y));
                        __half2 h1v = __floats2half2_rn(sigmoidf_(v1.x), sigmoidf_(v1.y));
                        uint2 st;
                        st.x = *(unsigned*)&h0v; st.y = *(unsigned*)&h1v;
                        *(uint2*)(o + p * 4) = st;
                    }
                }
            }
            __syncthreads();

            // ---- Level 1: thread=(kk 0..3, bp 0..7, hp 0..1, jl 0..3) ----
            //      2 b rows x 8 h x 32 k per thread; reduce over kk via shfl
            {
                const int kk = tid & 3;
                const int bp = (tid >> 2) & 7;
                const int hp = (tid >> 5) & 1;
                const int jl = tid >> 6;
                const float*  wB = sW1 + jl * 2064 + kk * 516 + hp * 8;
                const __half* aB = sH0 + (jl * 8 + kk * 2) * 324 + bp * 2 * 20;
                ull acc[2][4];
#pragma unroll
                for (int i = 0; i < 2; ++i)
#pragma unroll
                    for (int p = 0; p < 4; ++p) acc[i][p] = 0ull;

#pragma unroll
                for (int cc = 0; cc < 2; ++cc) {
                    const __half* aC = aB + cc * 324;
                    const float*  wC = wB + cc * 256;
#pragma unroll
                    for (int k4 = 0; k4 < 4; ++k4) {
                        ulonglong2 w0a = *(const ulonglong2*)(wC + (k4*4+0)*16);
                        ulonglong2 w0b = *(const ulonglong2*)(wC + (k4*4+0)*16 + 4);
                        ulonglong2 w1a = *(const ulonglong2*)(wC + (k4*4+1)*16);
                        ulonglong2 w1b = *(const ulonglong2*)(wC + (k4*4+1)*16 + 4);
                        ulonglong2 w2a = *(const ulonglong2*)(wC + (k4*4+2)*16);
                        ulonglong2 w2b = *(const ulonglong2*)(wC + (k4*4+2)*16 + 4);
                        ulonglong2 w3a = *(const ulonglong2*)(wC + (k4*4+3)*16);
                        ulonglong2 w3b = *(const ulonglong2*)(wC + (k4*4+3)*16 + 4);
#pragma unroll
                        for (int i = 0; i < 2; ++i) {
                            uint2 ar = *(const uint2*)(aC + i * 20 + k4 * 4);
                            float2 a01 = __half22float2(*(__half2*)&ar.x);
                            float2 a23 = __half22float2(*(__half2*)&ar.y);
                            ull a0 = pack2(a01.x, a01.x), a1 = pack2(a01.y, a01.y);
                            ull a2 = pack2(a23.x, a23.x), a3 = pack2(a23.y, a23.y);
                            fma2(acc[i][0], a0, w0a.x); fma2(acc[i][1], a0, w0a.y);
                            fma2(acc[i][2], a0, w0b.x); fma2(acc[i][3], a0, w0b.y);
                            fma2(acc[i][0], a1, w1a.x); fma2(acc[i][1], a1, w1a.y);
                            fma2(acc[i][2], a1, w1b.x); fma2(acc[i][3], a1, w1b.y);
                            fma2(acc[i][0], a2, w2a.x); fma2(acc[i][1], a2, w2a.y);
                            fma2(acc[i][2], a2, w2b.x); fma2(acc[i][3], a2, w2b.y);
                            fma2(acc[i][0], a3, w3a.x); fma2(acc[i][1], a3, w3a.y);
                            fma2(acc[i][2], a3, w3b.x); fma2(acc[i][3], a3, w3b.y);
                        }
                    }
                }
#pragma unroll
                for (int i = 0; i < 2; ++i)
#pragma unroll
                    for (int p = 0; p < 4; ++p) {
                        ull v = acc[i][p];
                        v = add2(v, __shfl_xor_sync(0xffffffffu, v, 1));
                        v = add2(v, __shfl_xor_sync(0xffffffffu, v, 2));
                        acc[i][p] = v;
                    }
                if (kk == 0) {
#pragma unroll
                    for (int i = 0; i < 2; ++i) {
                        int b = bp * 2 + i;
                        float* o = sH1 + b * 132 + (half * 4 + jl) * 16 + hp * 8;
                        float2 v0 = unpack2(acc[i][0]), v1 = unpack2(acc[i][1]);
                        float2 v2 = unpack2(acc[i][2]), v3 = unpack2(acc[i][3]);
                        float4 r0, r1;
                        r0.x = sigmoidf_(v0.x); r0.y = sigmoidf_(v0.y);
                        r0.z = sigmoidf_(v1.x); r0.w = sigmoidf_(v1.y);
                        r1.x = sigmoidf_(v2.x); r1.y = sigmoidf_(v2.y);
                        r1.z = sigmoidf_(v3.x); r1.w = sigmoidf_(v3.y);
                        *(float4*)o = r0;
                        *(float4*)(o + 4) = r1;
                    }
                }
            }
        }
        __syncthreads();   // H1 complete for this subtree

        // ---- Level 2: 128 threads, thread=(b 0..15, hp2 0..7) ----
        if (tid < 128) {
            const int b = tid & 15, hp2 = tid >> 4;
            const float* in = sH1 + b * 132;
            const float* w  = W2 + s2 * 2048 + hp2 * 2;
            ull acc = 0ull;
#pragma unroll
            for (int k4 = 0; k4 < 32; ++k4) {
                float4 a4 = *(const float4*)(in + k4 * 4);
                float av[4] = {a4.x, a4.y, a4.z, a4.w};
#pragma unroll
                for (int r = 0; r < 4; ++r) {
                    ull ad = pack2(av[r], av[r]);
                    ull wv = __ldg((const ull*)(w + (k4 * 4 + r) * 16));
                    fma2(acc, ad, wv);
                }
            }
            float2 v = unpack2(acc);
            float2 s; s.x = sigmoidf_(v.x); s.y = sigmoidf_(v.y);
            *(float2*)(sH2 + b * 132 + s2 * 16 + hp2 * 2) = s;
        }
    }
    __syncthreads();
    // sW1 region is dead: reuse for W3
    copy4(sW1, W3, 2048);
    __syncthreads();

    // ---- Root: 128 -> 16, sigmoid, scale by Wf ----
    {
        const int b = tid & 15, h = tid >> 4;
        const float* in = sH2 + b * 132;
        float acc = 0.f;
#pragma unroll
        for (int k4 = 0; k4 < 32; ++k4) {
            float4 a4 = *(const float4*)(in + k4 * 4);
            acc = fmaf(a4.x, sW1[(k4 * 4 + 0) * 16 + h], acc);
            acc = fmaf(a4.y, sW1[(k4 * 4 + 1) * 16 + h], acc);
            acc = fmaf(a4.z, sW1[(k4 * 4 + 2) * 16 + h], acc);
            acc = fmaf(a4.w, sW1[(k4 * 4 + 3) * 16 + h], acc);
        }
        sHr[b * 16 + h] = sigmoidf_(acc) * sWf[h];
    }
    __syncthreads();
    if (tid < 16) {
        const float* r = sHr + tid * 16;
        float acc = 0.f;
#pragma unroll
        for (int h = 0; h < 16; ++h) acc += r[h];
        out[b0 + tid] = acc;
    }
}

// ---------------------------------------------------------------------------
extern "C" void kernel_launch(void* const* d_in, const int* in_sizes, int n_in,
                              void* d_out, int out_size) {
    const float* x  = (const float*)d_in[0];
    const float* Wg = (const float*)d_in[1];
    const float* bg = (const float*)d_in[2];
    const float* W0 = (const float*)d_in[3];
    const float* W1 = (const float*)d_in[4];
    const float* W2 = (const float*)d_in[5];
    const float* W3 = (const float*)d_in[6];
    const float* Wf = (const float*)d_in[7];
    float* out = (float*)d_out;

    cudaFuncSetAttribute(fused_kernel,
                         cudaFuncAttributeMaxDynamicSharedMemorySize, SMEM_BYTES);

    prep_kernel<<<32, 256>>>(Wg, bg, W0);
    fused_kernel<<<NBLOCKS, NTHREADS, SMEM_BYTES>>>(x, W1, W2, W3, Wf, out);
}

// round 7
// speedup vs baseline: 2.0735x; 1.8641x over previous
#include <cuda_runtime.h>
#include <cuda_fp16.h>
#include <cstdint>

#define NTHREADS 256
#define TILE_B   16
#define NBLOCKS  (4096 / TILE_B)   // 256

// smem byte offsets
#define OFB_H0A 0                  // half [16][1032]  (row stride 2064 B)
#define OFB_H0B 33024
#define OFB_H1  66048              // half [16][1032]
#define OFB_H2  99072              // half [16][136]   (row stride 272 B)
#define SMEM_BYTES 103424
#define SH0_STRB 2064
#define SH2_STRB 272

// Pre-swizzled fp16 weight fragments (mma.sync .col B-operand order, per lane)
__device__ __align__(16) uint2 g_W0f[512 * 32];      // [m][lane]: {nh0 k-pair, nh1 k-pair}
__device__ __align__(16) uint4 g_W1f[64 * 32 * 8];   // [mod][lane][8]: 16 frags (kc,nh)
__device__ __align__(16) uint4 g_W2f[8 * 32 * 8];
__device__ __align__(16) uint4 g_W3f[32 * 8];

__device__ __forceinline__ float sigmoidf_(float v) {
    float t;
    asm("tanh.approx.f32 %0, %1;" : "=f"(t) : "f"(v * 0.5f));
    return fmaf(t, 0.5f, 0.5f);
}
__device__ __forceinline__ unsigned h2bits(__half2 h) { return *(unsigned*)&h; }

__device__ __forceinline__ void mma16816(float& c0, float& c1, float& c2, float& c3,
                                         unsigned a0, unsigned a1, unsigned a2, unsigned a3,
                                         unsigned b0, unsigned b1) {
    asm("mma.sync.aligned.m16n8k16.row.col.f32.f16.f16.f32 "
        "{%0,%1,%2,%3},{%4,%5,%6,%7},{%8,%9},{%0,%1,%2,%3};"
        : "+f"(c0), "+f"(c1), "+f"(c2), "+f"(c3)
        : "r"(a0), "r"(a1), "r"(a2), "r"(a3), "r"(b0), "r"(b1));
}
__device__ __forceinline__ void mma1688(float& c0, float& c1, float& c2, float& c3,
                                        unsigned a0, unsigned a1, unsigned b0) {
    asm("mma.sync.aligned.m16n8k8.row.col.f32.f16.f16.f32 "
        "{%0,%1,%2,%3},{%4,%5},{%6},{%0,%1,%2,%3};"
        : "+f"(c0), "+f"(c1), "+f"(c2), "+f"(c3)
        : "r"(a0), "r"(a1), "r"(b0));
}
__device__ __forceinline__ void ldmA(unsigned& r0, unsigned& r1, unsigned& r2, unsigned& r3,
                                     uint32_t addr) {
    asm volatile("ldmatrix.sync.aligned.m8n8.x4.shared.b16 {%0,%1,%2,%3},[%4];"
                 : "=r"(r0), "=r"(r1), "=r"(r2), "=r"(r3) : "r"(addr));
}

// ---------------------------------------------------------------------------
// Prep: build fragment-ordered fp16 weights
// ---------------------------------------------------------------------------
__global__ void prep_frags(const float* __restrict__ W0,
                           const float* __restrict__ W1,
                           const float* __restrict__ W2,
                           const float* __restrict__ W3) {
    int idx = blockIdx.x * blockDim.x + threadIdx.x;
    if (idx < 512 * 32) {                       // W0f: K=8, N=16
        int m = idx >> 5, lane = idx & 31;
        int k0 = (lane & 3) * 2, n = lane >> 2;
        const float* src = W0 + m * 128;        // [g][h]
        __half2 f0 = __floats2half2_rn(src[k0 * 16 + n], src[(k0 + 1) * 16 + n]);
        __half2 f1 = __floats2half2_rn(src[k0 * 16 + n + 8], src[(k0 + 1) * 16 + n + 8]);
        uint2 v; v.x = h2bits(f0); v.y = h2bits(f1);
        g_W0f[idx] = v;
        return;
    }
    int t = idx - 512 * 32;
    if (t >= 73 * 32) return;
    int mod = t >> 5, lane = t & 31;
    const float* src; uint4* dst;
    if (mod < 64)      { src = W1 + mod * 2048;        dst = g_W1f + (size_t)(mod * 32 + lane) * 8; }
    else if (mod < 72) { src = W2 + (mod - 64) * 2048; dst = g_W2f + (size_t)((mod - 64) * 32 + lane) * 8; }
    else               { src = W3;                     dst = g_W3f + (size_t)lane * 8; }
    // 16 frags: f = kc*2+nh ; frag = {B[k0][n],B[k0+1][n]},{B[k0+8][n],B[k0+9][n]}
#pragma unroll
    for (int kc = 0; kc < 8; ++kc) {
        uint4 o;
#pragma unroll
        for (int nh = 0; nh < 2; ++nh) {
            int k0 = kc * 16 + (lane & 3) * 2;
            int n  = nh * 8 + (lane >> 2);
            __half2 lo = __floats2half2_rn(src[k0 * 16 + n], src[(k0 + 1) * 16 + n]);
            __half2 hi = __floats2half2_rn(src[(k0 + 8) * 16 + n], src[(k0 + 9) * 16 + n]);
            if (nh == 0) { o.x = h2bits(lo); o.y = h2bits(hi); }
            else         { o.z = h2bits(lo); o.w = h2bits(hi); }
        }
        dst[kc] = o;
    }
}

// ---------------------------------------------------------------------------
extern __shared__ __align__(16) char smem_raw[];

// 16x128x16 GEMM: A (fp16, smem via ldmatrix) @ B (frag regs) -> C[2][4] fp32
__device__ __forceinline__ void gemm_16_128_16(uint32_t aAddr, const uint4* __restrict__ bp,
                                               float c[2][4]) {
    uint4 bv[8];
#pragma unroll
    for (int i = 0; i < 8; ++i) bv[i] = bp[i];
#pragma unroll
    for (int p = 0; p < 2; ++p)
#pragma unroll
        for (int q = 0; q < 4; ++q) c[p][q] = 0.f;
#pragma unroll
    for (int kc = 0; kc < 8; ++kc) {
        unsigned a0, a1, a2, a3;
        ldmA(a0, a1, a2, a3, aAddr + kc * 32);
        mma16816(c[0][0], c[0][1], c[0][2], c[0][3], a0, a1, a2, a3, bv[kc].x, bv[kc].y);
        mma16816(c[1][0], c[1][1], c[1][2], c[1][3], a0, a1, a2, a3, bv[kc].z, bv[kc].w);
    }
}

// store C (after sigmoid) to half buffer: rows lane>>2, +8 ; cols colBase + nh*8 + (lane&3)*2
__device__ __forceinline__ void store_sig_half(char* base, int strideB, int colBase,
                                               int lane, float c[2][4]) {
    int r0 = lane >> 2, cB = colBase + (lane & 3) * 2;
#pragma unroll
    for (int nh = 0; nh < 2; ++nh) {
        __half2 lo = __floats2half2_rn(sigmoidf_(c[nh][0]), sigmoidf_(c[nh][1]));
        __half2 hi = __floats2half2_rn(sigmoidf_(c[nh][2]), sigmoidf_(c[nh][3]));
        *(__half2*)(base + r0 * strideB + (cB + nh * 8) * 2) = lo;
        *(__half2*)(base + (r0 + 8) * strideB + (cB + nh * 8) * 2) = hi;
    }
}

__global__ void __launch_bounds__(NTHREADS, 2)
fused_kernel(const float* __restrict__ x,
             const float* __restrict__ Wg,
             const float* __restrict__ bg,
             const float* __restrict__ Wf,
             float* __restrict__ out) {
    const int tid  = threadIdx.x;
    const int lane = tid & 31;
    const int w    = tid >> 5;          // warp 0..7
    const int b0   = blockIdx.x * TILE_B;

    const uint32_t sbase = (uint32_t)__cvta_generic_to_shared(smem_raw);

    // per-lane constants for fragments
    const int r0 = lane >> 2;           // batch row (first)
    const int q2 = (lane & 3) * 2;      // col pair within frag

#pragma unroll 1
    for (int s2 = 0; s2 < 8; ++s2) {
        char* sH0 = smem_raw + ((s2 & 1) ? OFB_H0B : OFB_H0A);

        // ---- Level 0: warp w -> leaf modules mloc = w*8 .. w*8+7 ----
#pragma unroll 1
        for (int mm = 0; mm < 8; ++mm) {
            const int mloc = w * 8 + mm;
            const int m    = s2 * 64 + mloc;
            const float* xr0 = x + (((size_t)(b0 + r0)) << 12) + m * 8 + q2;
            float2 xa = *(const float2*)xr0;
            float2 xb = *(const float2*)(xr0 + (8ull << 12));
            float2 wgv = __ldg((const float2*)(Wg + m * 8 + q2));
            float2 bgv = __ldg((const float2*)(bg + m * 8 + q2));
            unsigned a0 = h2bits(__floats2half2_rn(fmaf(xa.x, wgv.x, bgv.x),
                                                   fmaf(xa.y, wgv.y, bgv.y)));
            unsigned a1 = h2bits(__floats2half2_rn(fmaf(xb.x, wgv.x, bgv.x),
                                                   fmaf(xb.y, wgv.y, bgv.y)));
            uint2 bf = g_W0f[m * 32 + lane];
            float c[2][4];
#pragma unroll
            for (int p = 0; p < 2; ++p)
#pragma unroll
                for (int q = 0; q < 4; ++q) c[p][q] = 0.f;
            mma1688(c[0][0], c[0][1], c[0][2], c[0][3], a0, a1, bf.x);
            mma1688(c[1][0], c[1][1], c[1][2], c[1][3], a0, a1, bf.y);
            store_sig_half(sH0, SH0_STRB, mloc * 16, lane, c);
        }
        __syncthreads();

        // ---- Level 1: warp w = module j ----
        {
            const int j = w;
            uint32_t aAddr = sbase + ((s2 & 1) ? OFB_H0B : OFB_H0A)
                           + (lane & 15) * SH0_STRB
                           + (j * 128 + ((lane >> 4) * 8)) * 2;
            float c[2][4];
            gemm_16_128_16(aAddr, g_W1f + (size_t)((s2 * 8 + j) * 32 + lane) * 8, c);
            store_sig_half(smem_raw + OFB_H1, SH0_STRB, s2 * 128 + j * 16, lane, c);
        }
        // no sync needed here: next level-0 writes the other H0 buffer,
        // and H1 cols for (s2, j) are written only by warp (s2, j).
    }
    __syncthreads();   // H1 complete

    // ---- Level 2: warp w = subtree w ----
    {
        uint32_t aAddr = sbase + OFB_H1 + (lane & 15) * SH0_STRB
                       + (w * 128 + ((lane >> 4) * 8)) * 2;
        float c[2][4];
        gemm_16_128_16(aAddr, g_W2f + (size_t)(w * 32 + lane) * 8, c);
        store_sig_half(smem_raw + OFB_H2, SH2_STRB, w * 16, lane, c);
    }
    __syncthreads();   // H2 complete

    // ---- Root (warp 0): [16,128]@[128,16], sigmoid, dot Wf, reduce ----
    if (w == 0) {
        uint32_t aAddr = sbase + OFB_H2 + (lane & 15) * SH2_STRB + ((lane >> 4) * 8) * 2;
        float c[2][4];
        gemm_16_128_16(aAddr, g_W3f + (size_t)lane * 8, c);
        float t0 = 0.f, t1 = 0.f;
#pragma unroll
        for (int nh = 0; nh < 2; ++nh) {
            float2 wf = __ldg((const float2*)(Wf + nh * 8 + q2));
            t0 += sigmoidf_(c[nh][0]) * wf.x + sigmoidf_(c[nh][1]) * wf.y;
            t1 += sigmoidf_(c[nh][2]) * wf.x + sigmoidf_(c[nh][3]) * wf.y;
        }
        t0 += __shfl_xor_sync(0xffffffffu, t0, 1);
        t0 += __shfl_xor_sync(0xffffffffu, t0, 2);
        t1 += __shfl_xor_sync(0xffffffffu, t1, 1);
        t1 += __shfl_xor_sync(0xffffffffu, t1, 2);
        if ((lane & 3) == 0) {
            out[b0 + r0] = t0;
            out[b0 + 8 + r0] = t1;
        }
    }
}

// ---------------------------------------------------------------------------
extern "C" void kernel_launch(void* const* d_in, const int* in_sizes, int n_in,
                              void* d_out, int out_size) {
    const float* x  = (const float*)d_in[0];
    const float* Wg = (const float*)d_in[1];
    const float* bg = (const float*)d_in[2];
    const float* W0 = (const float*)d_in[3];
    const float* W1 = (const float*)d_in[4];
    const float* W2 = (const float*)d_in[5];
    const float* W3 = (const float*)d_in[6];
    const float* Wf = (const float*)d_in[7];
    float* out = (float*)d_out;

    cudaFuncSetAttribute(fused_kernel,
                         cudaFuncAttributeMaxDynamicSharedMemorySize, SMEM_BYTES);

    // 512*32 + 73*32 = 18720 items
    prep_frags<<<74, 256>>>(W0, W1, W2, W3);
    fused_kernel<<<NBLOCKS, NTHREADS, SMEM_BYTES>>>(x, Wg, bg, Wf, out);
}

// round 10
// speedup vs baseline: 2.8804x; 1.3891x over previous
#include <cuda_runtime.h>
#include <cuda_fp16.h>
#include <cstdint>

#define NTHREADS 256
#define TILE_B   16
#define NBLOCKS  (4096 / TILE_B)   // 256

// smem byte offsets (H0 is warp-private: no double buffer needed)
#define OFB_H0  0                  // half [16][1032]  (row stride 2064 B)
#define OFB_H1  33024              // half [16][1032]
#define OFB_H2  66048              // half [16][136]   (row stride 272 B)
#define SMEM_BYTES 70400
#define SH0_STRB 2064
#define SH2_STRB 272

// Pre-swizzled fp16 weight fragments (mma.sync .col B-operand order, per lane)
__device__ __align__(16) uint2 g_W0f[512 * 32];      // [m][lane]
__device__ __align__(16) uint4 g_W1f[64 * 32 * 8];   // [mod][lane][8]
__device__ __align__(16) uint4 g_W2f[8 * 32 * 8];
__device__ __align__(16) uint4 g_W3f[32 * 8];

__device__ __forceinline__ float sigmoidf_(float v) {
    float t;
    asm("tanh.approx.f32 %0, %1;" : "=f"(t) : "f"(v * 0.5f));
    return fmaf(t, 0.5f, 0.5f);
}
__device__ __forceinline__ unsigned h2bits(__half2 h) { return *(unsigned*)&h; }

__device__ __forceinline__ void mma16816(float& c0, float& c1, float& c2, float& c3,
                                         unsigned a0, unsigned a1, unsigned a2, unsigned a3,
                                         unsigned b0, unsigned b1) {
    asm("mma.sync.aligned.m16n8k16.row.col.f32.f16.f16.f32 "
        "{%0,%1,%2,%3},{%4,%5,%6,%7},{%8,%9},{%0,%1,%2,%3};"
        : "+f"(c0), "+f"(c1), "+f"(c2), "+f"(c3)
        : "r"(a0), "r"(a1), "r"(a2), "r"(a3), "r"(b0), "r"(b1));
}
__device__ __forceinline__ void mma1688(float& c0, float& c1, float& c2, float& c3,
                                        unsigned a0, unsigned a1, unsigned b0) {
    asm("mma.sync.aligned.m16n8k8.row.col.f32.f16.f16.f32 "
        "{%0,%1,%2,%3},{%4,%5},{%6},{%0,%1,%2,%3};"
        : "+f"(c0), "+f"(c1), "+f"(c2), "+f"(c3)
        : "r"(a0), "r"(a1), "r"(b0));
}
__device__ __forceinline__ void ldmA(unsigned& r0, unsigned& r1, unsigned& r2, unsigned& r3,
                                     uint32_t addr) {
    asm volatile("ldmatrix.sync.aligned.m8n8.x4.shared.b16 {%0,%1,%2,%3},[%4];"
                 : "=r"(r0), "=r"(r1), "=r"(r2), "=r"(r3) : "r"(addr));
}

// ---------------------------------------------------------------------------
// Prep: build fragment-ordered fp16 weights
// ---------------------------------------------------------------------------
__global__ void prep_frags(const float* __restrict__ W0,
                           const float* __restrict__ W1,
                           const float* __restrict__ W2,
                           const float* __restrict__ W3) {
    int idx = blockIdx.x * blockDim.x + threadIdx.x;
    if (idx < 512 * 32) {                       // W0f: K=8, N=16
        int m = idx >> 5, lane = idx & 31;
        int k0 = (lane & 3) * 2, n = lane >> 2;
        const float* src = W0 + m * 128;        // [g][h]
        __half2 f0 = __floats2half2_rn(src[k0 * 16 + n], src[(k0 + 1) * 16 + n]);
        __half2 f1 = __floats2half2_rn(src[k0 * 16 + n + 8], src[(k0 + 1) * 16 + n + 8]);
        uint2 v; v.x = h2bits(f0); v.y = h2bits(f1);
        g_W0f[idx] = v;
        return;
    }
    int t = idx - 512 * 32;
    if (t >= 73 * 32) return;
    int mod = t >> 5, lane = t & 31;
    const float* src; uint4* dst;
    if (mod < 64)      { src = W1 + mod * 2048;        dst = g_W1f + (size_t)(mod * 32 + lane) * 8; }
    else if (mod < 72) { src = W2 + (mod - 64) * 2048; dst = g_W2f + (size_t)((mod - 64) * 32 + lane) * 8; }
    else               { src = W3;                     dst = g_W3f + (size_t)lane * 8; }
#pragma unroll
    for (int kc = 0; kc < 8; ++kc) {
        uint4 o;
#pragma unroll
        for (int nh = 0; nh < 2; ++nh) {
            int k0 = kc * 16 + (lane & 3) * 2;
            int n  = nh * 8 + (lane >> 2);
            __half2 lo = __floats2half2_rn(src[k0 * 16 + n], src[(k0 + 1) * 16 + n]);
            __half2 hi = __floats2half2_rn(src[(k0 + 8) * 16 + n], src[(k0 + 9) * 16 + n]);
            if (nh == 0) { o.x = h2bits(lo); o.y = h2bits(hi); }
            else         { o.z = h2bits(lo); o.w = h2bits(hi); }
        }
        dst[kc] = o;
    }
}

// ---------------------------------------------------------------------------
extern __shared__ __align__(16) char smem_raw[];

__device__ __forceinline__ void gemm_16_128_16(uint32_t aAddr, const uint4* __restrict__ bp,
                                               float c[2][4]) {
    uint4 bv[8];
#pragma unroll
    for (int i = 0; i < 8; ++i) bv[i] = bp[i];
#pragma unroll
    for (int p = 0; p < 2; ++p)
#pragma unroll
        for (int q = 0; q < 4; ++q) c[p][q] = 0.f;
#pragma unroll
    for (int kc = 0; kc < 8; ++kc) {
        unsigned a0, a1, a2, a3;
        ldmA(a0, a1, a2, a3, aAddr + kc * 32);
        mma16816(c[0][0], c[0][1], c[0][2], c[0][3], a0, a1, a2, a3, bv[kc].x, bv[kc].y);
        mma16816(c[1][0], c[1][1], c[1][2], c[1][3], a0, a1, a2, a3, bv[kc].z, bv[kc].w);
    }
}

__device__ __forceinline__ void store_sig_half(char* base, int strideB, int colBase,
                                               int lane, float c[2][4]) {
    int r0 = lane >> 2, cB = colBase + (lane & 3) * 2;
#pragma unroll
    for (int nh = 0; nh < 2; ++nh) {
        __half2 lo = __floats2half2_rn(sigmoidf_(c[nh][0]), sigmoidf_(c[nh][1]));
        __half2 hi = __floats2half2_rn(sigmoidf_(c[nh][2]), sigmoidf_(c[nh][3]));
        *(__half2*)(base + r0 * strideB + (cB + nh * 8) * 2) = lo;
        *(__half2*)(base + (r0 + 8) * strideB + (cB + nh * 8) * 2) = hi;
    }
}

__global__ void __launch_bounds__(NTHREADS, 3)
fused_kernel(const float* __restrict__ x,
             const float* __restrict__ Wg,
             const float* __restrict__ bg,
             const float* __restrict__ Wf,
             float* __restrict__ out) {
    const int tid  = threadIdx.x;
    const int lane = tid & 31;
    const int w    = tid >> 5;          // warp 0..7
    const int b0   = blockIdx.x * TILE_B;

    const uint32_t sbase = (uint32_t)__cvta_generic_to_shared(smem_raw);
    char* sH0 = smem_raw + OFB_H0;

    const int r0 = lane >> 2;           // batch row (first of pair)
    const int q2 = (lane & 3) * 2;      // col pair within frag

#pragma unroll 1
    for (int s2 = 0; s2 < 8; ++s2) {
        __syncwarp();   // prior level-1 reads of H0 done before overwrite

        // ---- Level 0: warp w -> leaf modules mloc = w*8..w*8+7 ----
        {
            // prefetch all 16 x loads (MLP=16)
            const float* xr0 = x + (((size_t)(b0 + r0)) << 12)
                             + s2 * 512 + w * 64 + q2;
            const float* xr1 = xr0 + (8ull << 12);
            float2 xa[8], xb[8];
#pragma unroll
            for (int mm = 0; mm < 8; ++mm) {
                xa[mm] = *(const float2*)(xr0 + mm * 8);
                xb[mm] = *(const float2*)(xr1 + mm * 8);
            }
            const float* wgp = Wg + (s2 * 64 + w * 8) * 8 + q2;
            const float* bgp = bg + (s2 * 64 + w * 8) * 8 + q2;
#pragma unroll
            for (int mm = 0; mm < 8; ++mm) {
                const int mloc = w * 8 + mm;
                const int m    = s2 * 64 + mloc;
                float2 wgv = __ldg((const float2*)(wgp + mm * 8));
                float2 bgv = __ldg((const float2*)(bgp + mm * 8));
                unsigned a0 = h2bits(__floats2half2_rn(fmaf(xa[mm].x, wgv.x, bgv.x),
                                                       fmaf(xa[mm].y, wgv.y, bgv.y)));
                unsigned a1 = h2bits(__floats2half2_rn(fmaf(xb[mm].x, wgv.x, bgv.x),
                                                       fmaf(xb[mm].y, wgv.y, bgv.y)));
                uint2 bf = g_W0f[m * 32 + lane];
                float c[2][4];
#pragma unroll
                for (int p = 0; p < 2; ++p)
#pragma unroll
                    for (int q = 0; q < 4; ++q) c[p][q] = 0.f;
                mma1688(c[0][0], c[0][1], c[0][2], c[0][3], a0, a1, bf.x);
                mma1688(c[1][0], c[1][1], c[1][2], c[1][3], a0, a1, bf.y);
                store_sig_half(sH0, SH0_STRB, mloc * 16, lane, c);
            }
        }
        __syncwarp();   // H0 (warp-private) visible to all lanes of this warp

        // ---- Level 1: warp w = module j = w (consumes its own H0 cols) ----
        {
            uint32_t aAddr = sbase + OFB_H0 + (lane & 15) * SH0_STRB
                           + (w * 128 + ((lane >> 4) * 8)) * 2;
            float c[2][4];
            gemm_16_128_16(aAddr, g_W1f + (size_t)((s2 * 8 + w) * 32 + lane) * 8, c);
            store_sig_half(smem_raw + OFB_H1, SH0_STRB, s2 * 128 + w * 16, lane, c);
        }
    }
    __syncthreads();   // H1 complete (cross-warp consumption next)

    // ---- Level 2: warp w = subtree w ----
    {
        uint32_t aAddr = sbase + OFB_H1 + (lane & 15) * SH0_STRB
                       + (w * 128 + ((lane >> 4) * 8)) * 2;
        float c[2][4];
        gemm_16_128_16(aAddr, g_W2f + (size_t)(w * 32 + lane) * 8, c);
        store_sig_half(smem_raw + OFB_H2, SH2_STRB, w * 16, lane, c);
    }
    __syncthreads();   // H2 complete

    // ---- Root (warp 0): [16,128]@[128,16], sigmoid, dot Wf, reduce ----
    if (w == 0) {
        uint32_t aAddr = sbase + OFB_H2 + (lane & 15) * SH2_STRB + ((lane >> 4) * 8) * 2;
        float c[2][4];
        gemm_16_128_16(aAddr, g_W3f + (size_t)lane * 8, c);
        float t0 = 0.f, t1 = 0.f;
#pragma unroll
        for (int nh = 0; nh < 2; ++nh) {
            float2 wf = __ldg((const float2*)(Wf + nh * 8 + q2));
            t0 += sigmoidf_(c[nh][0]) * wf.x + sigmoidf_(c[nh][1]) * wf.y;
            t1 += sigmoidf_(c[nh][2]) * wf.x + sigmoidf_(c[nh][3]) * wf.y;
        }
        t0 += __shfl_xor_sync(0xffffffffu, t0, 1);
        t0 += __shfl_xor_sync(0xffffffffu, t0, 2);
        t1 += __shfl_xor_sync(0xffffffffu, t1, 1);
        t1 += __shfl_xor_sync(0xffffffffu, t1, 2);
        if ((lane & 3) == 0) {
            out[b0 + r0] = t0;
            out[b0 + 8 + r0] = t1;
        }
    }
}

// ---------------------------------------------------------------------------
extern "C" void kernel_launch(void* const* d_in, const int* in_sizes, int n_in,
                              void* d_out, int out_size) {
    const float* x  = (const float*)d_in[0];
    const float* Wg = (const float*)d_in[1];
    const float* bg = (const float*)d_in[2];
    const float* W0 = (const float*)d_in[3];
    const float* W1 = (const float*)d_in[4];
    const float* W2 = (const float*)d_in[5];
    const float* W3 = (const float*)d_in[6];
    const float* Wf = (const float*)d_in[7];
    float* out = (float*)d_out;

    cudaFuncSetAttribute(fused_kernel,
                         cudaFuncAttributeMaxDynamicSharedMemorySize, SMEM_BYTES);

    prep_frags<<<74, 256>>>(W0, W1, W2, W3);
    fused_kernel<<<NBLOCKS, NTHREADS, SMEM_BYTES>>>(x, Wg, bg, Wf, out);
}

// round 11
// speedup vs baseline: 3.3097x; 1.1490x over previous
#include <cuda_runtime.h>
#include <cuda_fp16.h>
#include <cstdint>

#define NTHREADS 256
#define TILE_B   16
#define NBLOCKS  (4096 / TILE_B)   // 256

// smem: H0 eliminated (register-chained). H1 [16][1032]h, H2 [16][136]h
#define OFB_H1  0
#define OFB_H2  33024
#define SMEM_BYTES 37376
#define SH1_STRB 2064
#define SH2_STRB 272

// Fragment-ordered weights
__device__ __align__(16) uint2  g_W0f[512 * 32];     // folded Wg*W0, b-frag order
__device__ __align__(16) float4 g_c0f[512 * 4];      // bias c0 in c-frag order
__device__ __align__(16) uint4  g_W1f[64 * 32 * 8];
__device__ __align__(16) uint4  g_W2f[8 * 32 * 8];
__device__ __align__(16) uint4  g_W3f[32 * 8];

__device__ __forceinline__ float sigmoidf_(float v) {
    float t;
    asm("tanh.approx.f32 %0, %1;" : "=f"(t) : "f"(v * 0.5f));
    return fmaf(t, 0.5f, 0.5f);
}
__device__ __forceinline__ unsigned h2bits(__half2 h) { return *(unsigned*)&h; }

__device__ __forceinline__ void mma16816(float& c0, float& c1, float& c2, float& c3,
                                         unsigned a0, unsigned a1, unsigned a2, unsigned a3,
                                         unsigned b0, unsigned b1) {
    asm("mma.sync.aligned.m16n8k16.row.col.f32.f16.f16.f32 "
        "{%0,%1,%2,%3},{%4,%5,%6,%7},{%8,%9},{%0,%1,%2,%3};"
        : "+f"(c0), "+f"(c1), "+f"(c2), "+f"(c3)
        : "r"(a0), "r"(a1), "r"(a2), "r"(a3), "r"(b0), "r"(b1));
}
__device__ __forceinline__ void mma1688(float& c0, float& c1, float& c2, float& c3,
                                        unsigned a0, unsigned a1, unsigned b0) {
    asm("mma.sync.aligned.m16n8k8.row.col.f32.f16.f16.f32 "
        "{%0,%1,%2,%3},{%4,%5},{%6},{%0,%1,%2,%3};"
        : "+f"(c0), "+f"(c1), "+f"(c2), "+f"(c3)
        : "r"(a0), "r"(a1), "r"(b0));
}
__device__ __forceinline__ void ldmA(unsigned& r0, unsigned& r1, unsigned& r2, unsigned& r3,
                                     uint32_t addr) {
    asm volatile("ldmatrix.sync.aligned.m8n8.x4.shared.b16 {%0,%1,%2,%3},[%4];"
                 : "=r"(r0), "=r"(r1), "=r"(r2), "=r"(r3) : "r"(addr));
}

// ---------------------------------------------------------------------------
// Prep: fragment-ordered fp16 weights; Wg folded into W0, bias table c0f
// ---------------------------------------------------------------------------
__global__ void prep_frags(const float* __restrict__ Wg,
                           const float* __restrict__ bg,
                           const float* __restrict__ W0,
                           const float* __restrict__ W1,
                           const float* __restrict__ W2,
                           const float* __restrict__ W3) {
    int idx = blockIdx.x * blockDim.x + threadIdx.x;
    if (idx < 512 * 32) {                       // W0f (folded): K=8, N=16
        int m = idx >> 5, lane = idx & 31;
        int k0 = (lane & 3) * 2, n = lane >> 2;
        const float* src = W0 + m * 128;        // [g][h]
        float g0 = Wg[m * 8 + k0], g1 = Wg[m * 8 + k0 + 1];
        __half2 f0 = __floats2half2_rn(g0 * src[k0 * 16 + n],
                                       g1 * src[(k0 + 1) * 16 + n]);
        __half2 f1 = __floats2half2_rn(g0 * src[k0 * 16 + n + 8],
                                       g1 * src[(k0 + 1) * 16 + n + 8]);
        uint2 v; v.x = h2bits(f0); v.y = h2bits(f1);
        g_W0f[idx] = v;
        return;
    }
    int t = idx - 512 * 32;
    if (t < 512 * 4) {                          // c0f: bias in C-frag order
        int m = t >> 2, qq = t & 3;
        float4 o;
        float s0 = 0.f, s1 = 0.f, s2 = 0.f, s3 = 0.f;
#pragma unroll
        for (int g = 0; g < 8; ++g) {
            float b = bg[m * 8 + g];
            const float* wr = W0 + m * 128 + g * 16;
            s0 += b * wr[qq * 2];     s1 += b * wr[qq * 2 + 1];
            s2 += b * wr[qq * 2 + 8]; s3 += b * wr[qq * 2 + 9];
        }
        o.x = s0; o.y = s1; o.z = s2; o.w = s3;
        g_c0f[t] = o;
        return;
    }
    t -= 512 * 4;
    if (t >= 73 * 32) return;
    int mod = t >> 5, lane = t & 31;
    const float* src; uint4* dst;
    if (mod < 64)      { src = W1 + mod * 2048;        dst = g_W1f + (size_t)(mod * 32 + lane) * 8; }
    else if (mod < 72) { src = W2 + (mod - 64) * 2048; dst = g_W2f + (size_t)((mod - 64) * 32 + lane) * 8; }
    else               { src = W3;                     dst = g_W3f + (size_t)lane * 8; }
#pragma unroll
    for (int kc = 0; kc < 8; ++kc) {
        uint4 o;
#pragma unroll
        for (int nh = 0; nh < 2; ++nh) {
            int k0 = kc * 16 + (lane & 3) * 2;
            int n  = nh * 8 + (lane >> 2);
            __half2 lo = __floats2half2_rn(src[k0 * 16 + n], src[(k0 + 1) * 16 + n]);
            __half2 hi = __floats2half2_rn(src[(k0 + 8) * 16 + n], src[(k0 + 9) * 16 + n]);
            if (nh == 0) { o.x = h2bits(lo); o.y = h2bits(hi); }
            else         { o.z = h2bits(lo); o.w = h2bits(hi); }
        }
        dst[kc] = o;
    }
}

// ---------------------------------------------------------------------------
extern __shared__ __align__(16) char smem_raw[];

__device__ __forceinline__ void gemm_16_128_16(uint32_t aAddr, const uint4* __restrict__ bp,
                                               float c[2][4]) {
    uint4 bv[8];
#pragma unroll
    for (int i = 0; i < 8; ++i) bv[i] = bp[i];
#pragma unroll
    for (int p = 0; p < 2; ++p)
#pragma unroll
        for (int q = 0; q < 4; ++q) c[p][q] = 0.f;
#pragma unroll
    for (int kc = 0; kc < 8; ++kc) {
        unsigned a0, a1, a2, a3;
        ldmA(a0, a1, a2, a3, aAddr + kc * 32);
        mma16816(c[0][0], c[0][1], c[0][2], c[0][3], a0, a1, a2, a3, bv[kc].x, bv[kc].y);
        mma16816(c[1][0], c[1][1], c[1][2], c[1][3], a0, a1, a2, a3, bv[kc].z, bv[kc].w);
    }
}

__device__ __forceinline__ void store_sig_half(char* base, int strideB, int colBase,
                                               int lane, float c[2][4]) {
    int r0 = lane >> 2, cB = colBase + (lane & 3) * 2;
#pragma unroll
    for (int nh = 0; nh < 2; ++nh) {
        __half2 lo = __floats2half2_rn(sigmoidf_(c[nh][0]), sigmoidf_(c[nh][1]));
        __half2 hi = __floats2half2_rn(sigmoidf_(c[nh][2]), sigmoidf_(c[nh][3]));
        *(__half2*)(base + r0 * strideB + (cB + nh * 8) * 2) = lo;
        *(__half2*)(base + (r0 + 8) * strideB + (cB + nh * 8) * 2) = hi;
    }
}

__global__ void __launch_bounds__(NTHREADS, 2)
fused_kernel(const float* __restrict__ x,
             const float* __restrict__ Wf,
             float* __restrict__ out) {
    const int tid  = threadIdx.x;
    const int lane = tid & 31;
    const int w    = tid >> 5;          // warp 0..7
    const int b0   = blockIdx.x * TILE_B;

    const uint32_t sbase = (uint32_t)__cvta_generic_to_shared(smem_raw);

    const int r0 = lane >> 2;           // batch row (first of pair)
    const int q2 = (lane & 3) * 2;      // col pair within frag

    const size_t rowA = ((size_t)(b0 + r0)) << 12;
    const size_t rowB = rowA + (8ull << 12);
    const float* xpA = x + rowA + w * 64 + q2;
    const float* xpB = x + rowB + w * 64 + q2;

    float2 xa[8], xb[8];
#pragma unroll
    for (int mm = 0; mm < 8; ++mm) {
        xa[mm] = *(const float2*)(xpA + mm * 8);
        xb[mm] = *(const float2*)(xpB + mm * 8);
    }

#pragma unroll 1
    for (int s2 = 0; s2 < 8; ++s2) {
        // convert current x to fp16 A-frags (frees xa/xb for next prefetch)
        unsigned av0[8], av1[8];
#pragma unroll
        for (int mm = 0; mm < 8; ++mm) {
            av0[mm] = h2bits(__floats2half2_rn(xa[mm].x, xa[mm].y));
            av1[mm] = h2bits(__floats2half2_rn(xb[mm].x, xb[mm].y));
        }
        // prefetch next subtree's x (long latency, covered by MMA chain below)
        if (s2 < 7) {
            const float* pA = xpA + (s2 + 1) * 512;
            const float* pB = xpB + (s2 + 1) * 512;
#pragma unroll
            for (int mm = 0; mm < 8; ++mm) {
                xa[mm] = *(const float2*)(pA + mm * 8);
                xb[mm] = *(const float2*)(pB + mm * 8);
            }
        }
        // prefetch this subtree's W1 fragments (L2-resident)
        uint4 bv[8];
        {
            const uint4* bp = g_W1f + (size_t)((s2 * 8 + w) * 32 + lane) * 8;
#pragma unroll
            for (int kc = 0; kc < 8; ++kc) bv[kc] = bp[kc];
        }

        float acc[2][4];
#pragma unroll
        for (int p = 0; p < 2; ++p)
#pragma unroll
            for (int q = 0; q < 4; ++q) acc[p][q] = 0.f;

        // fused level-0 -> level-1: leaf kc's C-frag is level-1 chunk kc's A-frag
#pragma unroll
        for (int mm = 0; mm < 8; ++mm) {
            const int m = s2 * 64 + w * 8 + mm;
            float4 cf = g_c0f[m * 4 + (lane & 3)];
            uint2 bf = g_W0f[m * 32 + lane];
            float c0[4] = {cf.x, cf.y, cf.x, cf.y};
            float c1[4] = {cf.z, cf.w, cf.z, cf.w};
            mma1688(c0[0], c0[1], c0[2], c0[3], av0[mm], av1[mm], bf.x);
            mma1688(c1[0], c1[1], c1[2], c1[3], av0[mm], av1[mm], bf.y);
            unsigned f0 = h2bits(__floats2half2_rn(sigmoidf_(c0[0]), sigmoidf_(c0[1])));
            unsigned f1 = h2bits(__floats2half2_rn(sigmoidf_(c0[2]), sigmoidf_(c0[3])));
            unsigned f2 = h2bits(__floats2half2_rn(sigmoidf_(c1[0]), sigmoidf_(c1[1])));
            unsigned f3 = h2bits(__floats2half2_rn(sigmoidf_(c1[2]), sigmoidf_(c1[3])));
            mma16816(acc[0][0], acc[0][1], acc[0][2], acc[0][3],
                     f0, f1, f2, f3, bv[mm].x, bv[mm].y);
            mma16816(acc[1][0], acc[1][1], acc[1][2], acc[1][3],
                     f0, f1, f2, f3, bv[mm].z, bv[mm].w);
        }
        store_sig_half(smem_raw + OFB_H1, SH1_STRB, s2 * 128 + w * 16, lane, acc);
    }
    __syncthreads();   // H1 complete (cross-warp consumption next)

    // ---- Level 2: warp w = subtree w ----
    {
        uint32_t aAddr = sbase + OFB_H1 + (lane & 15) * SH1_STRB
                       + (w * 128 + ((lane >> 4) * 8)) * 2;
        float c[2][4];
        gemm_16_128_16(aAddr, g_W2f + (size_t)(w * 32 + lane) * 8, c);
        store_sig_half(smem_raw + OFB_H2, SH2_STRB, w * 16, lane, c);
    }
    __syncthreads();   // H2 complete

    // ---- Root (warp 0): [16,128]@[128,16], sigmoid, dot Wf, reduce ----
    if (w == 0) {
        uint32_t aAddr = sbase + OFB_H2 + (lane & 15) * SH2_STRB + ((lane >> 4) * 8) * 2;
        float c[2][4];
        gemm_16_128_16(aAddr, g_W3f + (size_t)lane * 8, c);
        float t0 = 0.f, t1 = 0.f;
#pragma unroll
        for (int nh = 0; nh < 2; ++nh) {
            float2 wf = __ldg((const float2*)(Wf + nh * 8 + q2));
            t0 += sigmoidf_(c[nh][0]) * wf.x + sigmoidf_(c[nh][1]) * wf.y;
            t1 += sigmoidf_(c[nh][2]) * wf.x + sigmoidf_(c[nh][3]) * wf.y;
        }
        t0 += __shfl_xor_sync(0xffffffffu, t0, 1);
        t0 += __shfl_xor_sync(0xffffffffu, t0, 2);
        t1 += __shfl_xor_sync(0xffffffffu, t1, 1);
        t1 += __shfl_xor_sync(0xffffffffu, t1, 2);
        if ((lane & 3) == 0) {
            out[b0 + r0] = t0;
            out[b0 + 8 + r0] = t1;
        }
    }
}

// ---------------------------------------------------------------------------
extern "C" void kernel_launch(void* const* d_in, const int* in_sizes, int n_in,
                              void* d_out, int out_size) {
    const float* x  = (const float*)d_in[0];
    const float* Wg = (const float*)d_in[1];
    const float* bg = (const float*)d_in[2];
    const float* W0 = (const float*)d_in[3];
    const float* W1 = (const float*)d_in[4];
    const float* W2 = (const float*)d_in[5];
    const float* W3 = (const float*)d_in[6];
    const float* Wf = (const float*)d_in[7];
    float* out = (float*)d_out;

    cudaFuncSetAttribute(fused_kernel,
                         cudaFuncAttributeMaxDynamicSharedMemorySize, SMEM_BYTES);

    // 512*32 + 512*4 + 73*32 = 20768 items
    prep_frags<<<82, 256>>>(Wg, bg, W0, W1, W2, W3);
    fused_kernel<<<NBLOCKS, NTHREADS, SMEM_BYTES>>>(x, Wf, out);
}